// round 4
// baseline (speedup 1.0000x reference)
#include <cuda_runtime.h>
#include <math.h>

#define EC_MAX 64
#define BLK 256
#define PTS 4
#define PTS_PER_BLK (BLK * PTS)
#define MAX_BLOCKS 4096

__device__ float g_pen_part[MAX_BLOCKS];
__device__ int   g_ctr = 0;          // last-block-done counter (reset each replay)

// sigmoid via single HW MUFU tanh: sigma(x) = 0.5*tanh(x/2) + 0.5
__device__ __forceinline__ float fsig(float x) {
    float t;
    asm("tanh.approx.f32 %0, %1;" : "=f"(t) : "f"(x * 0.5f));
    return fmaf(t, 0.5f, 0.5f);
}

// Per-element packed params in smem: 3 float4 per element:
//  p0 = {cx, cy, cz, |const|}   p1 = {c00, c01, c02, c11}   p2 = {c12, c22, -, -}
__device__ __forceinline__ void compute_params(
    float4* sp, int ec,
    const float* __restrict__ constants,
    const float* __restrict__ centers,
    const float* __restrict__ radii,
    const float* __restrict__ rotations)
{
    int e = threadIdx.x;
    if (e < ec) {
        float cx0 = centers[3*e+0];
        float cy0 = centers[3*e+1];
        float cz0 = centers[3*e+2];
        float cab = fabsf(constants[e]);
        float d0 = __fdividef(1.0f, fabsf(radii[3*e+0]) + 0.005f + 1e-8f);
        float d1 = __fdividef(1.0f, fabsf(radii[3*e+1]) + 0.005f + 1e-8f);
        float d2 = __fdividef(1.0f, fabsf(radii[3*e+2]) + 0.005f + 1e-8f);

        float sx, cx, sy, cy, sz, cz;
        __sincosf(rotations[3*e+0], &sx, &cx);
        __sincosf(rotations[3*e+1], &sy, &cy);
        __sincosf(rotations[3*e+2], &sz, &cz);

        float R00 = cz * cy;
        float R01 = cz * sy * sx - sz * cx;
        float R02 = cz * sy * cx + sz * sx;
        float R10 = sz * cy;
        float R11 = sz * sy * sx + cz * cx;
        float R12 = sz * sy * cx - cz * sx;
        float R20 = -sy;
        float R21 = cy * sx;
        float R22 = cy * cx;

        float c00 = R00*R00*d0 + R01*R01*d1 + R02*R02*d2;
        float c01 = R00*R10*d0 + R01*R11*d1 + R02*R12*d2;
        float c02 = R00*R20*d0 + R01*R21*d1 + R02*R22*d2;
        float c11 = R10*R10*d0 + R11*R11*d1 + R12*R12*d2;
        float c12 = R10*R20*d0 + R11*R21*d1 + R12*R22*d2;
        float c22 = R20*R20*d0 + R21*R21*d1 + R22*R22*d2;

        sp[e*3 + 0] = make_float4(cx0, cy0, cz0, cab);
        sp[e*3 + 1] = make_float4(c00, c01, c02, c11);
        sp[e*3 + 2] = make_float4(c12, c22, 0.0f, 0.0f);
    }
}

__global__ void __launch_bounds__(BLK) rbf_main(
    const float* __restrict__ wsp,
    const float4* __restrict__ act,
    const float* __restrict__ dists,
    float4* __restrict__ out,
    const float* __restrict__ constants,
    const float* __restrict__ centers,
    const float* __restrict__ radii,
    const float* __restrict__ rotations,
    int N, int ec, int out_size)
{
    __shared__ float4 sp[EC_MAX * 3];
    __shared__ float wpen[BLK / 32];
    __shared__ bool s_last;

    int tid = threadIdx.x;
    compute_params(sp, ec, constants, centers, radii, rotations);
    __syncthreads();

    int base = blockIdx.x * PTS_PER_BLK + tid;
    bool all_valid = (blockIdx.x + 1) * PTS_PER_BLK <= N;

    int   nn[PTS];
    bool  vv[PTS];
    float px[PTS], py[PTS], pz[PTS], dd[PTS];
    float sum[PTS], ax[PTS], ay[PTS], az[PTS], aw[PTS];
    float pen = 0.0f;

    #pragma unroll
    for (int p = 0; p < PTS; ++p) {
        nn[p] = base + p * BLK;
        vv[p] = all_valid || (nn[p] < N);
        px[p] = py[p] = pz[p] = dd[p] = 0.0f;
        if (vv[p]) {
            px[p] = wsp[3*nn[p]+0];
            py[p] = wsp[3*nn[p]+1];
            pz[p] = wsp[3*nn[p]+2];
            dd[p] = dists[nn[p]];
        }
        sum[p] = ax[p] = ay[p] = az[p] = aw[p] = 0.0f;
    }

    #pragma unroll 2
    for (int e = 0; e < ec; ++e) {
        float4 p0 = sp[e*3 + 0];
        float4 p1 = sp[e*3 + 1];
        float4 p2 = sp[e*3 + 2];

        float4 a[PTS];
        const float4* col = act + (size_t)e * N;
        #pragma unroll
        for (int p = 0; p < PTS; ++p)
            a[p] = vv[p] ? __ldcs(&col[nn[p]]) : make_float4(0,0,0,0);

        #pragma unroll
        for (int p = 0; p < PTS; ++p) {
            float dx = px[p] - p0.x, dy = py[p] - p0.y, dz = pz[p] - p0.z;
            float tx = fmaf(p1.x, dx, fmaf(p1.y, dy, p1.z * dz));
            float ty = fmaf(p1.y, dx, fmaf(p1.w, dy, p2.x * dz));
            float tz = fmaf(p1.z, dx, fmaf(p2.x, dy, p2.y * dz));
            float q  = fmaf(dx, tx, fmaf(dy, ty, dz * tz));
            float rbf = __expf(-0.5f * q) * p0.w;
            sum[p] += rbf;
            pen    += fmaxf(rbf - 0.01f, 0.0f);
            float alpha = 1.0f - __expf(-fmaxf(a[p].w, 0.0f) * dd[p]);
            ax[p] = fmaf(rbf, fsig(a[p].x), ax[p]);
            ay[p] = fmaf(rbf, fsig(a[p].y), ay[p]);
            az[p] = fmaf(rbf, fsig(a[p].z), az[p]);
            aw[p] = fmaf(rbf, alpha, aw[p]);
        }
    }

    #pragma unroll
    for (int p = 0; p < PTS; ++p) {
        if (vv[p]) {
            float winv = __fdividef(1.0f, sum[p] + 1e-6f);
            out[nn[p]] = make_float4(ax[p]*winv, ay[p]*winv, az[p]*winv, aw[p]*winv);
        }
    }

    // block penalty reduction
    #pragma unroll
    for (int off = 16; off; off >>= 1)
        pen += __shfl_xor_sync(0xffffffffu, pen, off);
    if ((tid & 31) == 0) wpen[tid >> 5] = pen;
    __syncthreads();
    if (tid == 0) {
        float s = 0.0f;
        #pragma unroll
        for (int w = 0; w < BLK / 32; ++w) s += wpen[w];
        g_pen_part[blockIdx.x] = s;
        __threadfence();
        int done = atomicAdd(&g_ctr, 1);
        s_last = (done == (int)gridDim.x - 1);
    }
    __syncthreads();

    // last finished block reduces all partials + bbox penalty, writes scalar,
    // and resets the counter so every graph replay starts identically.
    if (s_last) {
        float s = 0.0f;
        for (int i = tid; i < (int)gridDim.x; i += BLK) s += g_pen_part[i];
        if (tid < ec) {
            float cx0 = centers[3*tid+0], cy0 = centers[3*tid+1], cz0 = centers[3*tid+2];
            float bp = fmaxf(cx0 - 0.6f, 0.0f) + fmaxf(-0.6f  - cx0, 0.0f)
                     + fmaxf(cy0 - 0.6f, 0.0f) + fmaxf(-0.6f  - cy0, 0.0f)
                     + fmaxf(cz0 - 0.6f, 0.0f) + fmaxf(-0.35f - cz0, 0.0f);
            s += bp * (float)N * 1000.0f;   // undo the 0.001/N scale below
        }
        #pragma unroll
        for (int off = 16; off; off >>= 1)
            s += __shfl_xor_sync(0xffffffffu, s, off);
        if ((tid & 31) == 0) wpen[tid >> 5] = s;
        __syncthreads();
        if (tid == 0) {
            float tot = 0.0f;
            #pragma unroll
            for (int w = 0; w < BLK / 32; ++w) tot += wpen[w];
            if (out_size > 4 * N)
                ((float*)out)[out_size - 1] = 0.001f * tot / (float)N;
            g_ctr = 0;
        }
    }
}

extern "C" void kernel_launch(void* const* d_in, const int* in_sizes, int n_in,
                              void* d_out, int out_size) {
    const float*  wsp       = (const float*)d_in[0];
    const float4* act       = (const float4*)d_in[1];
    const float*  dists     = (const float*)d_in[2];
    const float*  constants = (const float*)d_in[3];
    const float*  centers   = (const float*)d_in[4];
    const float*  radii     = (const float*)d_in[5];
    const float*  rotations = (const float*)d_in[6];

    int N  = in_sizes[0] / 3;
    int ec = in_sizes[3];
    if (ec > EC_MAX) ec = EC_MAX;

    int blocks = (N + PTS_PER_BLK - 1) / PTS_PER_BLK;
    if (blocks > MAX_BLOCKS) blocks = MAX_BLOCKS;  // N fits for this problem
    rbf_main<<<blocks, BLK>>>(wsp, act, dists, (float4*)d_out,
                              constants, centers, radii, rotations, N, ec, out_size);
}

// round 7
// speedup vs baseline: 2.1408x; 2.1408x over previous
#include <cuda_runtime.h>
#include <math.h>

#define EC_MAX 64
#define BLK 128
#define PTS 2
#define PTS_PER_BLK (BLK * PTS)
#define MAX_BLOCKS 8192

__device__ float g_pen_part[MAX_BLOCKS];
__device__ int   g_ctr = 0;          // last-block-done counter (reset each replay)

// sigmoid via single HW MUFU tanh: sigma(x) = 0.5*tanh(x/2) + 0.5
__device__ __forceinline__ float fsig(float x) {
    float t;
    asm("tanh.approx.f32 %0, %1;" : "=f"(t) : "f"(x * 0.5f));
    return fmaf(t, 0.5f, 0.5f);
}

// Per-element packed params in smem: 3 float4 per element:
//  p0 = {cx, cy, cz, |const|}   p1 = {c00, c01, c02, c11}   p2 = {c12, c22, -, -}
__device__ __forceinline__ void compute_params(
    float4* sp, int ec,
    const float* __restrict__ constants,
    const float* __restrict__ centers,
    const float* __restrict__ radii,
    const float* __restrict__ rotations)
{
    int e = threadIdx.x;
    if (e < ec) {
        float cx0 = centers[3*e+0];
        float cy0 = centers[3*e+1];
        float cz0 = centers[3*e+2];
        float cab = fabsf(constants[e]);
        float d0 = __fdividef(1.0f, fabsf(radii[3*e+0]) + 0.005f + 1e-8f);
        float d1 = __fdividef(1.0f, fabsf(radii[3*e+1]) + 0.005f + 1e-8f);
        float d2 = __fdividef(1.0f, fabsf(radii[3*e+2]) + 0.005f + 1e-8f);

        float sx, cx, sy, cy, sz, cz;
        __sincosf(rotations[3*e+0], &sx, &cx);
        __sincosf(rotations[3*e+1], &sy, &cy);
        __sincosf(rotations[3*e+2], &sz, &cz);

        float R00 = cz * cy;
        float R01 = cz * sy * sx - sz * cx;
        float R02 = cz * sy * cx + sz * sx;
        float R10 = sz * cy;
        float R11 = sz * sy * sx + cz * cx;
        float R12 = sz * sy * cx - cz * sx;
        float R20 = -sy;
        float R21 = cy * sx;
        float R22 = cy * cx;

        float c00 = R00*R00*d0 + R01*R01*d1 + R02*R02*d2;
        float c01 = R00*R10*d0 + R01*R11*d1 + R02*R12*d2;
        float c02 = R00*R20*d0 + R01*R21*d1 + R02*R22*d2;
        float c11 = R10*R10*d0 + R11*R11*d1 + R12*R12*d2;
        float c12 = R10*R20*d0 + R11*R21*d1 + R12*R22*d2;
        float c22 = R20*R20*d0 + R21*R21*d1 + R22*R22*d2;

        sp[e*3 + 0] = make_float4(cx0, cy0, cz0, cab);
        sp[e*3 + 1] = make_float4(c00, c01, c02, c11);
        sp[e*3 + 2] = make_float4(c12, c22, 0.0f, 0.0f);
    }
}

__global__ void __launch_bounds__(BLK) rbf_main(
    const float* __restrict__ wsp,
    const float4* __restrict__ act,
    const float* __restrict__ dists,
    float4* __restrict__ out,
    const float* __restrict__ constants,
    const float* __restrict__ centers,
    const float* __restrict__ radii,
    const float* __restrict__ rotations,
    int N, int ec, int out_size)
{
    __shared__ float4 sp[EC_MAX * 3];
    __shared__ float wpen[BLK / 32];
    __shared__ bool s_last;

    int tid = threadIdx.x;
    compute_params(sp, ec, constants, centers, radii, rotations);
    __syncthreads();

    int n0 = blockIdx.x * PTS_PER_BLK + tid;
    int n1 = n0 + BLK;
    bool v0 = n0 < N, v1 = n1 < N;

    float px0=0,py0=0,pz0=0,dist0=0, px1=0,py1=0,pz1=0,dist1=0;
    if (v0) { px0 = wsp[3*n0]; py0 = wsp[3*n0+1]; pz0 = wsp[3*n0+2]; dist0 = dists[n0]; }
    if (v1) { px1 = wsp[3*n1]; py1 = wsp[3*n1+1]; pz1 = wsp[3*n1+2]; dist1 = dists[n1]; }

    float sum0=0, ax0=0, ay0=0, az0=0, aw0=0;
    float sum1=0, ax1=0, ay1=0, az1=0, aw1=0;
    float pen = 0.0f;

    #pragma unroll 4
    for (int e = 0; e < ec; ++e) {
        float4 p0 = sp[e*3 + 0];
        float4 p1 = sp[e*3 + 1];
        float4 p2 = sp[e*3 + 2];

        const float4* col = act + (size_t)e * N;
        float4 a0 = v0 ? __ldcs(&col[n0]) : make_float4(0,0,0,0);
        float4 a1 = v1 ? __ldcs(&col[n1]) : make_float4(0,0,0,0);

        {
            float dx = px0 - p0.x, dy = py0 - p0.y, dz = pz0 - p0.z;
            float tx = fmaf(p1.x, dx, fmaf(p1.y, dy, p1.z * dz));
            float ty = fmaf(p1.y, dx, fmaf(p1.w, dy, p2.x * dz));
            float tz = fmaf(p1.z, dx, fmaf(p2.x, dy, p2.y * dz));
            float q  = fmaf(dx, tx, fmaf(dy, ty, dz * tz));
            float rbf = __expf(-0.5f * q) * p0.w;
            sum0 += rbf;
            pen  += fmaxf(rbf - 0.01f, 0.0f);
            float alpha = 1.0f - __expf(-fmaxf(a0.w, 0.0f) * dist0);
            ax0 = fmaf(rbf, fsig(a0.x), ax0);
            ay0 = fmaf(rbf, fsig(a0.y), ay0);
            az0 = fmaf(rbf, fsig(a0.z), az0);
            aw0 = fmaf(rbf, alpha, aw0);
        }
        {
            float dx = px1 - p0.x, dy = py1 - p0.y, dz = pz1 - p0.z;
            float tx = fmaf(p1.x, dx, fmaf(p1.y, dy, p1.z * dz));
            float ty = fmaf(p1.y, dx, fmaf(p1.w, dy, p2.x * dz));
            float tz = fmaf(p1.z, dx, fmaf(p2.x, dy, p2.y * dz));
            float q  = fmaf(dx, tx, fmaf(dy, ty, dz * tz));
            float rbf = __expf(-0.5f * q) * p0.w;
            sum1 += rbf;
            pen  += fmaxf(rbf - 0.01f, 0.0f);
            float alpha = 1.0f - __expf(-fmaxf(a1.w, 0.0f) * dist1);
            ax1 = fmaf(rbf, fsig(a1.x), ax1);
            ay1 = fmaf(rbf, fsig(a1.y), ay1);
            az1 = fmaf(rbf, fsig(a1.z), az1);
            aw1 = fmaf(rbf, alpha, aw1);
        }
    }

    if (v0) {
        float winv = __fdividef(1.0f, sum0 + 1e-6f);
        out[n0] = make_float4(ax0*winv, ay0*winv, az0*winv, aw0*winv);
    }
    if (v1) {
        float winv = __fdividef(1.0f, sum1 + 1e-6f);
        out[n1] = make_float4(ax1*winv, ay1*winv, az1*winv, aw1*winv);
    }

    // block penalty reduction
    #pragma unroll
    for (int off = 16; off; off >>= 1)
        pen += __shfl_xor_sync(0xffffffffu, pen, off);
    if ((tid & 31) == 0) wpen[tid >> 5] = pen;
    __syncthreads();
    if (tid == 0) {
        float s = 0.0f;
        #pragma unroll
        for (int w = 0; w < BLK / 32; ++w) s += wpen[w];
        g_pen_part[blockIdx.x] = s;
        __threadfence();
        int done = atomicAdd(&g_ctr, 1);
        s_last = (done == (int)gridDim.x - 1);
    }
    __syncthreads();

    // last finished block reduces all partials + bbox penalty, writes scalar,
    // resets counter for deterministic graph replay.
    if (s_last) {
        float s = 0.0f;
        for (int i = tid; i < (int)gridDim.x; i += BLK) s += g_pen_part[i];
        if (tid < ec) {
            float cx0 = centers[3*tid+0], cy0 = centers[3*tid+1], cz0 = centers[3*tid+2];
            float bp = fmaxf(cx0 - 0.6f, 0.0f) + fmaxf(-0.6f  - cx0, 0.0f)
                     + fmaxf(cy0 - 0.6f, 0.0f) + fmaxf(-0.6f  - cy0, 0.0f)
                     + fmaxf(cz0 - 0.6f, 0.0f) + fmaxf(-0.35f - cz0, 0.0f);
            s += bp * (float)N * 1000.0f;   // undo the 0.001/N scale below
        }
        #pragma unroll
        for (int off = 16; off; off >>= 1)
            s += __shfl_xor_sync(0xffffffffu, s, off);
        if ((tid & 31) == 0) wpen[tid >> 5] = s;
        __syncthreads();
        if (tid == 0) {
            float tot = 0.0f;
            #pragma unroll
            for (int w = 0; w < BLK / 32; ++w) tot += wpen[w];
            if (out_size > 4 * N)
                ((float*)out)[out_size - 1] = 0.001f * tot / (float)N;
            g_ctr = 0;
        }
    }
}

extern "C" void kernel_launch(void* const* d_in, const int* in_sizes, int n_in,
                              void* d_out, int out_size) {
    const float*  wsp       = (const float*)d_in[0];
    const float4* act       = (const float4*)d_in[1];
    const float*  dists     = (const float*)d_in[2];
    const float*  constants = (const float*)d_in[3];
    const float*  centers   = (const float*)d_in[4];
    const float*  radii     = (const float*)d_in[5];
    const float*  rotations = (const float*)d_in[6];

    int N  = in_sizes[0] / 3;
    int ec = in_sizes[3];
    if (ec > EC_MAX) ec = EC_MAX;

    int blocks = (N + PTS_PER_BLK - 1) / PTS_PER_BLK;
    if (blocks > MAX_BLOCKS) blocks = MAX_BLOCKS;  // N fits for this problem
    rbf_main<<<blocks, BLK>>>(wsp, act, dists, (float4*)d_out,
                              constants, centers, radii, rotations, N, ec, out_size);
}